// round 5
// baseline (speedup 1.0000x reference)
#include <cuda_runtime.h>

#define HID      64
#define NCLASS   100
#define MAXN     100000
#define MAXE     1600000
#define NGRAPH_MAX 512
#define ID_OFFSET 1500
#define BN_EPS   1e-5f

// Scratch (no cudaMalloc allowed): node features ping (h) / work (x), pooled, BN stats
__device__ float4 g_h4[MAXN * 16];              // [N][64] as float4[N][16]
__device__ float4 g_x4[MAXN * 16];
__device__ float4 g_pooled4[NGRAPH_MAX * 48];   // [G][192] as float4[G][48]
__device__ float  g_stats[3 * 128];             // per layer: 64 sums, 64 sumsq

__device__ __forceinline__ void red_add_v4(float4* addr, float4 v) {
    asm volatile("red.global.add.v4.f32 [%0], {%1, %2, %3, %4};"
                 :: "l"(addr), "f"(v.x), "f"(v.y), "f"(v.z), "f"(v.w)
                 : "memory");
}

// ---- packed f32x2 helpers (Blackwell sm_103a) --------------------------------
__device__ __forceinline__ unsigned long long pack2(float a, float b) {
    unsigned long long r;
    asm("mov.b64 %0, {%1, %2};" : "=l"(r) : "f"(a), "f"(b));
    return r;
}
__device__ __forceinline__ void fma2(unsigned long long& d,
                                     unsigned long long a, unsigned long long b) {
    asm("fma.rn.f32x2 %0, %1, %2, %0;" : "+l"(d) : "l"(a), "l"(b));
}
__device__ __forceinline__ void unpack2(unsigned long long v, float& a, float& b) {
    asm("mov.b64 {%0, %1}, %2;" : "=f"(a), "=f"(b) : "l"(v));
}

// ---------------------------------------------------------------- zero scratch
__global__ void zero_kernel() {
    int i = blockIdx.x * blockDim.x + threadIdx.x;
    if (i < NGRAPH_MAX * 48) g_pooled4[i] = make_float4(0.f, 0.f, 0.f, 0.f);
    if (i < 3 * 128)         g_stats[i] = 0.f;
}

// -------------------------------------------- h = emb[ids+1500]; x = (1+eps0)*h
__global__ void gather_kernel(const int* __restrict__ node_ids,
                              const float4* __restrict__ emb4,
                              const float* __restrict__ eps, int N) {
    int i = blockIdx.x * blockDim.x + threadIdx.x;
    if (i >= N * 16) return;
    int node = i >> 4, c = i & 15;
    int id = __ldg(&node_ids[node]) + ID_OFFSET;
    float4 v = __ldg(&emb4[id * 16 + c]);
    g_h4[i] = v;
    float s = 1.f + __ldg(eps);
    g_x4[i] = make_float4(v.x * s, v.y * s, v.z * s, v.w * s);
}

// ------------------------------------------------ x[dst] += h[src] over edges
__global__ void scatter_kernel(const int* __restrict__ src,
                               const int* __restrict__ dst, int E) {
    int i = blockIdx.x * blockDim.x + threadIdx.x;
    if (i >= E * 16) return;
    int e = i >> 4, c = i & 15;
    int s = __ldg(&src[e]);
    int d = __ldg(&dst[e]);
    float4 v = g_h4[s * 16 + c];
    red_add_v4(&g_x4[d * 16 + c], v);
}

// --------------------------- x = relu(relu(relu(x W0 + b0) W1 + b1) W2 + b2)
// Packed f32x2 version: acc holds output j-pairs; per-k broadcast pack of x.
__global__ void __launch_bounds__(128) mlp_kernel(const float4* __restrict__ Ws4,
                                                  const float* __restrict__ bs,
                                                  int l, int N) {
    __shared__ float4 sWraw[1024];   // one 64x64 W, row-major [k][j/4]
    __shared__ float4 sb4[16];
    const ulonglong2* sW2 = (const ulonglong2*)sWraw;   // [k][16] (2 j-pairs each)
    const ulonglong2* sb2 = (const ulonglong2*)sb4;

    int node = blockIdx.x * 128 + threadIdx.x;
    bool active = node < N;

    float x[64];
    if (active) {
        #pragma unroll
        for (int c = 0; c < 16; c++) {
            float4 v = g_x4[node * 16 + c];
            x[4*c] = v.x; x[4*c+1] = v.y; x[4*c+2] = v.z; x[4*c+3] = v.w;
        }
    }

    for (int m = 0; m < 3; m++) {
        __syncthreads();
        const float4* W4 = Ws4 + (l * 3 + m) * 1024;
        for (int t = threadIdx.x; t < 1024; t += 128) sWraw[t] = __ldg(&W4[t]);
        if (threadIdx.x < 16) {
            const float4* b4 = (const float4*)(bs + (l * 3 + m) * 64);
            sb4[threadIdx.x] = __ldg(&b4[threadIdx.x]);
        }
        __syncthreads();

        if (active) {
            // acc[i] = packed pair (y[2i], y[2i+1])
            unsigned long long acc[32];
            #pragma unroll
            for (int q = 0; q < 16; q++) {
                ulonglong2 b = sb2[q];
                acc[2*q]   = b.x;
                acc[2*q+1] = b.y;
            }
            #pragma unroll 16
            for (int k = 0; k < 64; k++) {
                unsigned long long xv = pack2(x[k], x[k]);
                #pragma unroll
                for (int q = 0; q < 16; q++) {
                    ulonglong2 w = sW2[k * 16 + q];
                    fma2(acc[2*q],   xv, w.x);   // (y4q, y4q+1) += (x,x)*(W[k][4q],W[k][4q+1])
                    fma2(acc[2*q+1], xv, w.y);   // (y4q+2,y4q+3)
                }
            }
            // ReLU back into scalar x
            #pragma unroll
            for (int i = 0; i < 32; i++) {
                float a, b;
                unpack2(acc[i], a, b);
                x[2*i]   = fmaxf(a, 0.f);
                x[2*i+1] = fmaxf(b, 0.f);
            }
        }
    }

    if (active) {
        #pragma unroll
        for (int c = 0; c < 16; c++)
            g_x4[node * 16 + c] = make_float4(x[4*c], x[4*c+1], x[4*c+2], x[4*c+3]);
    }
}

// -------------------------------------- per-feature sum / sumsq over x (for BN)
__global__ void stats_kernel(int l, int N) {
    __shared__ float4 ssum[256];
    __shared__ float4 ssq[256];
    int tid = threadIdx.x;
    int f4 = tid & 15;      // which float4 of features
    int r  = tid >> 4;      // row lane 0..15
    float4 s = make_float4(0.f, 0.f, 0.f, 0.f);
    float4 q = make_float4(0.f, 0.f, 0.f, 0.f);
    for (int row = blockIdx.x * 16 + r; row < N; row += gridDim.x * 16) {
        float4 v = g_x4[row * 16 + f4];
        s.x += v.x; s.y += v.y; s.z += v.z; s.w += v.w;
        q.x += v.x * v.x; q.y += v.y * v.y; q.z += v.z * v.z; q.w += v.w * v.w;
    }
    ssum[tid] = s; ssq[tid] = q;
    __syncthreads();
    for (int half = 8; half >= 1; half >>= 1) {
        if (r < half) {
            float4 a = ssum[tid + half * 16];
            float4 b = ssq [tid + half * 16];
            float4 cs = ssum[tid], cq = ssq[tid];
            cs.x += a.x; cs.y += a.y; cs.z += a.z; cs.w += a.w;
            cq.x += b.x; cq.y += b.y; cq.z += b.z; cq.w += b.w;
            ssum[tid] = cs; ssq[tid] = cq;
        }
        __syncthreads();
    }
    if (r == 0) {
        float4 cs = ssum[tid], cq = ssq[tid];
        atomicAdd(&g_stats[l*128 + f4*4 + 0], cs.x);
        atomicAdd(&g_stats[l*128 + f4*4 + 1], cs.y);
        atomicAdd(&g_stats[l*128 + f4*4 + 2], cs.z);
        atomicAdd(&g_stats[l*128 + f4*4 + 3], cs.w);
        atomicAdd(&g_stats[l*128 + 64 + f4*4 + 0], cq.x);
        atomicAdd(&g_stats[l*128 + 64 + f4*4 + 1], cq.y);
        atomicAdd(&g_stats[l*128 + 64 + f4*4 + 2], cq.z);
        atomicAdd(&g_stats[l*128 + 64 + f4*4 + 3], cq.w);
    }
}

// --- h = BN(x); pooled[g] += h; x_next = (1+eps[l+1])*h (fused next-layer init)
__global__ void finalize_kernel(const int* __restrict__ graph_ids,
                                const float* __restrict__ gamma,
                                const float* __restrict__ beta,
                                const float* __restrict__ eps,
                                int l, int N) {
    int i = blockIdx.x * blockDim.x + threadIdx.x;
    if (i >= N * 16) return;
    int node = i >> 4, c = i & 15;
    float invN = 1.f / (float)N;
    float sc[4], sh[4];
    #pragma unroll
    for (int j = 0; j < 4; j++) {
        int f = c * 4 + j;
        float su = g_stats[l*128 + f];
        float sq = g_stats[l*128 + 64 + f];
        float mean = su * invN;
        float var  = sq * invN - mean * mean;
        float gm = __ldg(&gamma[l*64 + f]);
        float bt = __ldg(&beta [l*64 + f]);
        float s = gm * rsqrtf(var + BN_EPS);
        sc[j] = s;
        sh[j] = bt - mean * s;
    }
    float4 v = g_x4[i];
    float4 h;
    h.x = v.x * sc[0] + sh[0];
    h.y = v.y * sc[1] + sh[1];
    h.z = v.z * sc[2] + sh[2];
    h.w = v.w * sc[3] + sh[3];
    g_h4[i] = h;
    if (l < 2) {
        float s = 1.f + __ldg(&eps[l + 1]);
        g_x4[i] = make_float4(h.x * s, h.y * s, h.z * s, h.w * s);
    }
    int g = __ldg(&graph_ids[node]);
    red_add_v4(&g_pooled4[g * 48 + l * 16 + c], h);
}

// ----------------------------------------- out[g] = pooled[g] @ W_out + b_out
__global__ void out_kernel(const float* __restrict__ W_out,
                           const float* __restrict__ b_out,
                           float* __restrict__ out, int G) {
    __shared__ float sp[192];
    int g = blockIdx.x;
    const float* prow = (const float*)g_pooled4 + g * 192;
    if (threadIdx.x < 192) sp[threadIdx.x] = prow[threadIdx.x];
    __syncthreads();
    int c = threadIdx.x;
    if (c < NCLASS) {
        float acc = __ldg(&b_out[c]);
        #pragma unroll 8
        for (int k = 0; k < 192; k++)
            acc = fmaf(sp[k], __ldg(&W_out[k * NCLASS + c]), acc);
        out[g * NCLASS + c] = acc;
    }
}

extern "C" void kernel_launch(void* const* d_in, const int* in_sizes, int n_in,
                              void* d_out, int out_size) {
    const int*   node_ids  = (const int*)  d_in[0];
    const int*   edge_src  = (const int*)  d_in[1];
    const int*   edge_dst  = (const int*)  d_in[2];
    const int*   graph_ids = (const int*)  d_in[3];
    const float* emb       = (const float*)d_in[4];
    const float* Ws        = (const float*)d_in[5];
    const float* bs        = (const float*)d_in[6];
    const float* bn_gamma  = (const float*)d_in[7];
    const float* bn_beta   = (const float*)d_in[8];
    const float* eps       = (const float*)d_in[9];
    const float* W_out     = (const float*)d_in[10];
    const float* b_out     = (const float*)d_in[11];
    float* out = (float*)d_out;

    int N = in_sizes[0];
    int E = in_sizes[1];
    int G = out_size / NCLASS;

    int gN = (N * 16 + 255) / 256;
    int gE = (E * 16 + 255) / 256;

    zero_kernel<<<96, 256>>>();
    gather_kernel<<<gN, 256>>>(node_ids, (const float4*)emb, eps, N);
    for (int l = 0; l < 3; l++) {
        scatter_kernel<<<gE, 256>>>(edge_src, edge_dst, E);
        mlp_kernel<<<(N + 127) / 128, 128>>>((const float4*)Ws, bs, l, N);
        stats_kernel<<<512, 256>>>(l, N);
        finalize_kernel<<<gN, 256>>>(graph_ids, bn_gamma, bn_beta, eps, l, N);
    }
    out_kernel<<<G, 192>>>(W_out, b_out, out, G);
}

// round 7
// speedup vs baseline: 1.2395x; 1.2395x over previous
#include <cuda_runtime.h>

#define HID      64
#define NCLASS   100
#define MAXN     100000
#define MAXE     1600000
#define NGRAPH_MAX 512
#define ID_OFFSET 1500
#define BN_EPS   1e-5f
#define MLP_BLOCK 96   // 3 warps, 96 nodes per block

// Scratch (no cudaMalloc allowed)
__device__ float4 g_h4[MAXN * 16];              // [N][64] as float4[N][16]
__device__ float4 g_x4[MAXN * 16];
__device__ float4 g_pooled4[NGRAPH_MAX * 48];   // [G][192] as float4[G][48]
__device__ float  g_stats[3 * 128];             // per layer: 64 sums, 64 sumsq

__device__ __forceinline__ void red_add_v4(float4* addr, float4 v) {
    asm volatile("red.global.add.v4.f32 [%0], {%1, %2, %3, %4};"
                 :: "l"(addr), "f"(v.x), "f"(v.y), "f"(v.z), "f"(v.w)
                 : "memory");
}

// ---- packed f32x2 helpers (Blackwell sm_103a) --------------------------------
__device__ __forceinline__ unsigned long long pack2(float a, float b) {
    unsigned long long r;
    asm("mov.b64 %0, {%1, %2};" : "=l"(r) : "f"(a), "f"(b));
    return r;
}
__device__ __forceinline__ void fma2(unsigned long long& d,
                                     unsigned long long a, unsigned long long b) {
    asm("fma.rn.f32x2 %0, %1, %2, %0;" : "+l"(d) : "l"(a), "l"(b));
}
__device__ __forceinline__ void unpack2(unsigned long long v, float& a, float& b) {
    asm("mov.b64 {%0, %1}, %2;" : "=f"(a), "=f"(b) : "l"(v));
}

// ---------------------------------------------------------------- zero scratch
__global__ void zero_kernel() {
    int i = blockIdx.x * blockDim.x + threadIdx.x;
    if (i < NGRAPH_MAX * 48) g_pooled4[i] = make_float4(0.f, 0.f, 0.f, 0.f);
    if (i < 3 * 128)         g_stats[i] = 0.f;
}

// -------------------------------------------- h = emb[ids+1500]; x = (1+eps0)*h
__global__ void gather_kernel(const int* __restrict__ node_ids,
                              const float4* __restrict__ emb4,
                              const float* __restrict__ eps, int N) {
    int i = blockIdx.x * blockDim.x + threadIdx.x;
    if (i >= N * 16) return;
    int node = i >> 4, c = i & 15;
    int id = __ldg(&node_ids[node]) + ID_OFFSET;
    float4 v = __ldg(&emb4[id * 16 + c]);
    g_h4[i] = v;
    float s = 1.f + __ldg(eps);
    g_x4[i] = make_float4(v.x * s, v.y * s, v.z * s, v.w * s);
}

// ------------------------------------------------ x[dst] += h[src] over edges
__global__ void scatter_kernel(const int* __restrict__ src,
                               const int* __restrict__ dst, int E) {
    int i = blockIdx.x * blockDim.x + threadIdx.x;
    if (i >= E * 16) return;
    int e = i >> 4, c = i & 15;
    int s = __ldg(&src[e]);
    int d = __ldg(&dst[e]);
    float4 v = g_h4[s * 16 + c];
    red_add_v4(&g_x4[d * 16 + c], v);
}

// --------------------------- x = relu(relu(relu(x W0 + b0) W1 + b1) W2 + b2)
// Crossbar-optimized: each lane owns 4 nodes (ng = lane&7) x 16 outputs
// (jc = lane>>3). x staged in SMEM (stride 65, conflict-free). W tile stored
// with per-row swizzle (q+jc)&3 so the 4 distinct jc addresses of each
// warp-wide LDS.128 hit distinct bank quads. Delivered smem bytes per warp
// per k: 4*512B (W) + 128B (x) vs 8192B in the broadcast design.
__global__ void __launch_bounds__(MLP_BLOCK) mlp_kernel(const float4* __restrict__ Ws4,
                                                        const float* __restrict__ bs,
                                                        int l, int N) {
    __shared__ float  sx[MLP_BLOCK * 65];   // 96 x 64 node features, stride 65
    __shared__ float4 sW4[1024];            // one 64x64 W, swizzled
    __shared__ float4 sb4[16];

    int tid  = threadIdx.x;
    int warp = tid >> 5, lane = tid & 31;
    int ng = lane & 7, jc = lane >> 3;
    int nodeBase = blockIdx.x * MLP_BLOCK;
    int nl0 = warp * 32 + ng * 4;           // this lane's first local node

    // ---- stage x into SMEM (coalesced: 6 nodes x 16 float4 per round) ----
    #pragma unroll
    for (int r = 0; r < 16; r++) {
        int node_l = r * 6 + (tid >> 4);
        int c = tid & 15;
        int node = nodeBase + node_l;
        float4 v = (node < N) ? g_x4[node * 16 + c] : make_float4(0.f,0.f,0.f,0.f);
        int b = node_l * 65 + c * 4;
        sx[b] = v.x; sx[b+1] = v.y; sx[b+2] = v.z; sx[b+3] = v.w;
    }

    const ulonglong2* sW2 = (const ulonglong2*)sW4;

    for (int m = 0; m < 3; m++) {
        __syncthreads();
        const float4* W4 = Ws4 + (l * 3 + m) * 1024;
        for (int t = tid; t < 1024; t += MLP_BLOCK) {
            int k = t >> 4, c = t & 15;
            int jj = c >> 2, q = c & 3;
            sW4[k * 16 + jj * 4 + ((q + jj) & 3)] = __ldg(&W4[t]);
        }
        if (tid < 16) {
            const float4* b4 = (const float4*)(bs + (l * 3 + m) * 64);
            sb4[tid] = __ldg(&b4[tid]);
        }
        __syncthreads();

        const unsigned long long* sbU = (const unsigned long long*)sb4;
        unsigned long long acc[4][8];   // [node i][output pair p] of chunk jc
        #pragma unroll
        for (int p = 0; p < 8; p++) {
            unsigned long long bv = sbU[jc * 8 + p];
            acc[0][p] = bv; acc[1][p] = bv; acc[2][p] = bv; acc[3][p] = bv;
        }

        #pragma unroll 4
        for (int k = 0; k < 64; k++) {
            unsigned long long xp[4];
            #pragma unroll
            for (int i = 0; i < 4; i++) {
                float xv = sx[(nl0 + i) * 65 + k];
                xp[i] = pack2(xv, xv);
            }
            #pragma unroll
            for (int q = 0; q < 4; q++) {
                ulonglong2 w = sW2[k * 16 + jc * 4 + ((q + jc) & 3)];
                #pragma unroll
                for (int i = 0; i < 4; i++) {
                    fma2(acc[i][2*q],   xp[i], w.x);
                    fma2(acc[i][2*q+1], xp[i], w.y);
                }
            }
        }

        if (m < 2) {
            __syncwarp();   // sx rows are warp-private: readers done before rewrite
            #pragma unroll
            for (int i = 0; i < 4; i++) {
                #pragma unroll
                for (int p = 0; p < 8; p++) {
                    float a, b; unpack2(acc[i][p], a, b);
                    int base = (nl0 + i) * 65 + jc * 16 + 2 * p;
                    sx[base]     = fmaxf(a, 0.f);
                    sx[base + 1] = fmaxf(b, 0.f);
                }
            }
        } else {
            #pragma unroll
            for (int i = 0; i < 4; i++) {
                int node = nodeBase + nl0 + i;
                if (node < N) {
                    #pragma unroll
                    for (int q = 0; q < 4; q++) {
                        float a, b, c2, d;
                        unpack2(acc[i][2*q],   a, b);
                        unpack2(acc[i][2*q+1], c2, d);
                        g_x4[node * 16 + jc * 4 + q] =
                            make_float4(fmaxf(a,0.f), fmaxf(b,0.f),
                                        fmaxf(c2,0.f), fmaxf(d,0.f));
                    }
                }
            }
        }
    }
}

// -------------------------------------- per-feature sum / sumsq over x (for BN)
__global__ void stats_kernel(int l, int N) {
    __shared__ float4 ssum[256];
    __shared__ float4 ssq[256];
    int tid = threadIdx.x;
    int f4 = tid & 15;      // which float4 of features
    int r  = tid >> 4;      // row lane 0..15
    float4 s = make_float4(0.f, 0.f, 0.f, 0.f);
    float4 q = make_float4(0.f, 0.f, 0.f, 0.f);
    for (int row = blockIdx.x * 16 + r; row < N; row += gridDim.x * 16) {
        float4 v = g_x4[row * 16 + f4];
        s.x += v.x; s.y += v.y; s.z += v.z; s.w += v.w;
        q.x += v.x * v.x; q.y += v.y * v.y; q.z += v.z * v.z; q.w += v.w * v.w;
    }
    ssum[tid] = s; ssq[tid] = q;
    __syncthreads();
    for (int half = 8; half >= 1; half >>= 1) {
        if (r < half) {
            float4 a = ssum[tid + half * 16];
            float4 b = ssq [tid + half * 16];
            float4 cs = ssum[tid], cq = ssq[tid];
            cs.x += a.x; cs.y += a.y; cs.z += a.z; cs.w += a.w;
            cq.x += b.x; cq.y += b.y; cq.z += b.z; cq.w += b.w;
            ssum[tid] = cs; ssq[tid] = cq;
        }
        __syncthreads();
    }
    if (r == 0) {
        float4 cs = ssum[tid], cq = ssq[tid];
        atomicAdd(&g_stats[l*128 + f4*4 + 0], cs.x);
        atomicAdd(&g_stats[l*128 + f4*4 + 1], cs.y);
        atomicAdd(&g_stats[l*128 + f4*4 + 2], cs.z);
        atomicAdd(&g_stats[l*128 + f4*4 + 3], cs.w);
        atomicAdd(&g_stats[l*128 + 64 + f4*4 + 0], cq.x);
        atomicAdd(&g_stats[l*128 + 64 + f4*4 + 1], cq.y);
        atomicAdd(&g_stats[l*128 + 64 + f4*4 + 2], cq.z);
        atomicAdd(&g_stats[l*128 + 64 + f4*4 + 3], cq.w);
    }
}

// --- h = BN(x); pooled[g] += h; x_next = (1+eps[l+1])*h (fused next-layer init)
__global__ void finalize_kernel(const int* __restrict__ graph_ids,
                                const float* __restrict__ gamma,
                                const float* __restrict__ beta,
                                const float* __restrict__ eps,
                                int l, int N) {
    int i = blockIdx.x * blockDim.x + threadIdx.x;
    if (i >= N * 16) return;
    int node = i >> 4, c = i & 15;
    float invN = 1.f / (float)N;
    float sc[4], sh[4];
    #pragma unroll
    for (int j = 0; j < 4; j++) {
        int f = c * 4 + j;
        float su = g_stats[l*128 + f];
        float sq = g_stats[l*128 + 64 + f];
        float mean = su * invN;
        float var  = sq * invN - mean * mean;
        float gm = __ldg(&gamma[l*64 + f]);
        float bt = __ldg(&beta [l*64 + f]);
        float s = gm * rsqrtf(var + BN_EPS);
        sc[j] = s;
        sh[j] = bt - mean * s;
    }
    float4 v = g_x4[i];
    float4 h;
    h.x = v.x * sc[0] + sh[0];
    h.y = v.y * sc[1] + sh[1];
    h.z = v.z * sc[2] + sh[2];
    h.w = v.w * sc[3] + sh[3];
    g_h4[i] = h;
    if (l < 2) {
        float s = 1.f + __ldg(&eps[l + 1]);
        g_x4[i] = make_float4(h.x * s, h.y * s, h.z * s, h.w * s);
    }
    int g = __ldg(&graph_ids[node]);
    red_add_v4(&g_pooled4[g * 48 + l * 16 + c], h);
}

// ----------------------------------------- out[g] = pooled[g] @ W_out + b_out
__global__ void out_kernel(const float* __restrict__ W_out,
                           const float* __restrict__ b_out,
                           float* __restrict__ out, int G) {
    __shared__ float sp[192];
    int g = blockIdx.x;
    const float* prow = (const float*)g_pooled4 + g * 192;
    if (threadIdx.x < 192) sp[threadIdx.x] = prow[threadIdx.x];
    __syncthreads();
    int c = threadIdx.x;
    if (c < NCLASS) {
        float acc = __ldg(&b_out[c]);
        #pragma unroll 8
        for (int k = 0; k < 192; k++)
            acc = fmaf(sp[k], __ldg(&W_out[k * NCLASS + c]), acc);
        out[g * NCLASS + c] = acc;
    }
}

extern "C" void kernel_launch(void* const* d_in, const int* in_sizes, int n_in,
                              void* d_out, int out_size) {
    const int*   node_ids  = (const int*)  d_in[0];
    const int*   edge_src  = (const int*)  d_in[1];
    const int*   edge_dst  = (const int*)  d_in[2];
    const int*   graph_ids = (const int*)  d_in[3];
    const float* emb       = (const float*)d_in[4];
    const float* Ws        = (const float*)d_in[5];
    const float* bs        = (const float*)d_in[6];
    const float* bn_gamma  = (const float*)d_in[7];
    const float* bn_beta   = (const float*)d_in[8];
    const float* eps       = (const float*)d_in[9];
    const float* W_out     = (const float*)d_in[10];
    const float* b_out     = (const float*)d_in[11];
    float* out = (float*)d_out;

    int N = in_sizes[0];
    int E = in_sizes[1];
    int G = out_size / NCLASS;

    int gN = (N * 16 + 255) / 256;
    int gE = (E * 16 + 255) / 256;

    zero_kernel<<<96, 256>>>();
    gather_kernel<<<gN, 256>>>(node_ids, (const float4*)emb, eps, N);
    for (int l = 0; l < 3; l++) {
        scatter_kernel<<<gE, 256>>>(edge_src, edge_dst, E);
        mlp_kernel<<<(N + MLP_BLOCK - 1) / MLP_BLOCK, MLP_BLOCK>>>((const float4*)Ws, bs, l, N);
        stats_kernel<<<512, 256>>>(l, N);
        finalize_kernel<<<gN, 256>>>(graph_ids, bn_gamma, bn_beta, eps, l, N);
    }
    out_kernel<<<G, 192>>>(W_out, b_out, out, G);
}